// round 2
// baseline (speedup 1.0000x reference)
#include <cuda_runtime.h>

#define NN   100000
#define NE   1600000
#define FIN  128
#define DIM  32
#define NC   40

// ---------------- scratch (device globals — no runtime alloc) ----------------
__device__ __align__(16) float g_y   [(size_t)NN * DIM];
__device__ __align__(16) float g_aggY[(size_t)NN * DIM];
__device__ __align__(16) float g_z   [(size_t)NN * DIM];
__device__ __align__(16) float g_aggZ[(size_t)NN * DIM];
__device__ __align__(16) int   g_src [NE];
__device__ __align__(16) int   g_dst [NE];
__device__ int g_is64;
__device__ __align__(16) float g_W2a [DIM * DIM];   // diag(s1) @ w2a
__device__ __align__(16) float g_c2a [DIM];         // (bn1_b - bn1_m*s1) @ w2a
__device__ __align__(16) float g_W2b [DIM * DIM];   // w2b @ diag(s2)
__device__ __align__(16) float g_bb2 [DIM];         // (b2b - bn2_m)*s2 + bn2_b

// ---------------- detect edge_index dtype (int32 vs int64) ----------------
// int64 values < 2^31 => every odd int32 word is 0. For int32 data the odd
// words are random node ids in [0, 1e5) -> essentially never all zero.
__global__ void k_detect(const int* __restrict__ ei32) {
    if (threadIdx.x == 0) {
        int all_zero = 1;
        for (int i = 1; i < 128; i += 2)
            if (ei32[i] != 0) { all_zero = 0; break; }
        g_is64 = all_zero;
    }
}

// ---------------- decode edge_index into flat int32 src/dst ----------------
__global__ void __launch_bounds__(256) k_decode(const int* __restrict__ ei32) {
    int e = blockIdx.x * blockDim.x + threadIdx.x;
    if (e >= NE) return;
    if (g_is64) {
        g_src[e] = ei32[2 * (size_t)e];
        g_dst[e] = ei32[2 * ((size_t)NE + e)];
    } else {
        g_src[e] = ei32[e];
        g_dst[e] = ei32[NE + e];
    }
}

// ---------------- fold BN into weights (1 tiny block) ----------------
__global__ void k_setup(const float* __restrict__ w2a,
                        const float* __restrict__ bn1_g, const float* __restrict__ bn1_b,
                        const float* __restrict__ bn1_m, const float* __restrict__ bn1_v,
                        const float* __restrict__ w2b,  const float* __restrict__ b2b,
                        const float* __restrict__ bn2_g, const float* __restrict__ bn2_b,
                        const float* __restrict__ bn2_m, const float* __restrict__ bn2_v) {
    int tid = threadIdx.x;            // 1024 threads: tid = k*32 + j
    int k = tid >> 5, j = tid & 31;
    float s1k = bn1_g[k] * rsqrtf(bn1_v[k] + 1e-5f);
    g_W2a[tid] = s1k * w2a[tid];
    float s2j = bn2_g[j] * rsqrtf(bn2_v[j] + 1e-5f);
    g_W2b[tid] = w2b[tid] * s2j;
    if (tid < DIM) {
        float c = 0.f;
        for (int kk = 0; kk < DIM; kk++) {
            float s = bn1_g[kk] * rsqrtf(bn1_v[kk] + 1e-5f);
            c += (bn1_b[kk] - bn1_m[kk] * s) * w2a[kk * DIM + tid];
        }
        g_c2a[tid] = c;
        float s2 = bn2_g[tid] * rsqrtf(bn2_v[tid] + 1e-5f);
        g_bb2[tid] = (b2b[tid] - bn2_m[tid]) * s2 + bn2_b[tid];
    }
}

// ---------------- zero both accumulators ----------------
__global__ void k_zero() {
    int i = blockIdx.x * blockDim.x + threadIdx.x;
    if (i < NN * DIM / 4) {
        float4 z = make_float4(0.f, 0.f, 0.f, 0.f);
        ((float4*)g_aggY)[i] = z;
        ((float4*)g_aggZ)[i] = z;
    }
}

// ---------------- K1: y = x @ w1a  (N x 128 @ 128 x 32) ----------------
__global__ void __launch_bounds__(256) k_gemm1(const float* __restrict__ x,
                                               const float* __restrict__ w1a) {
    __shared__ float4 ws[FIN * (DIM / 4)];            // 16 KB
    for (int i = threadIdx.x; i < FIN * DIM / 4; i += 256)
        ws[i] = ((const float4*)w1a)[i];
    __syncthreads();

    int n = blockIdx.x * 256 + threadIdx.x;
    if (n >= NN) return;

    float acc[DIM];
#pragma unroll
    for (int j = 0; j < DIM; j++) acc[j] = 0.f;

    const float4* xr = (const float4*)(x + (size_t)n * FIN);
    for (int kk = 0; kk < FIN / 4; kk++) {
        float4 xv = xr[kk];
        const float4* wr = &ws[kk * 4 * 8];
#pragma unroll
        for (int u = 0; u < 4; u++) {
            float xs = (u == 0) ? xv.x : (u == 1) ? xv.y : (u == 2) ? xv.z : xv.w;
#pragma unroll
            for (int j4 = 0; j4 < 8; j4++) {
                float4 w = wr[u * 8 + j4];
                acc[j4 * 4 + 0] += xs * w.x;
                acc[j4 * 4 + 1] += xs * w.y;
                acc[j4 * 4 + 2] += xs * w.z;
                acc[j4 * 4 + 3] += xs * w.w;
            }
        }
    }
    float4* yr = (float4*)(g_y + (size_t)n * DIM);
#pragma unroll
    for (int j4 = 0; j4 < 8; j4++)
        yr[j4] = make_float4(acc[4*j4], acc[4*j4+1], acc[4*j4+2], acc[4*j4+3]);
}

// ---------------- edge aggregation: agg[dst] += feat[src] ----------------
template <int PASS>
__global__ void __launch_bounds__(256) k_agg() {
    int e = blockIdx.x * blockDim.x + threadIdx.x;
    if (e >= NE) return;
    int s = g_src[e];
    int d = g_dst[e];
    const float* feat = (PASS == 0) ? g_y    : g_z;
    float*       agg  = (PASS == 0) ? g_aggY : g_aggZ;
    const float4* fr = (const float4*)(feat + (size_t)s * DIM);
    float* ar = agg + (size_t)d * DIM;
    float4 v[8];
#pragma unroll
    for (int i = 0; i < 8; i++) v[i] = __ldg(&fr[i]);
#pragma unroll
    for (int i = 0; i < 8; i++) {
        unsigned long long ga = (unsigned long long)__cvta_generic_to_global(ar + i * 4);
        asm volatile("red.global.add.v4.f32 [%0], {%1,%2,%3,%4};"
                     :: "l"(ga),
                        "f"(v[i].x), "f"(v[i].y), "f"(v[i].z), "f"(v[i].w)
                     : "memory");
    }
}

// ---------------- K3: z = relu(relu(aggY+y+b1a)@w1b + b1b) @ W2a' + c' ----------------
__global__ void __launch_bounds__(256) k_mlp1(const float* __restrict__ b1a,
                                              const float* __restrict__ w1b,
                                              const float* __restrict__ b1b) {
    __shared__ float4 w1b_s[DIM * 8];
    __shared__ float4 w2a_s[DIM * 8];
    __shared__ float b1a_s[DIM], b1b_s[DIM], c2a_s[DIM];
    int t = threadIdx.x;
    for (int i = t; i < DIM * 8; i += 256) {
        w1b_s[i] = ((const float4*)w1b)[i];
        w2a_s[i] = ((const float4*)g_W2a)[i];
    }
    if (t < DIM) { b1a_s[t] = b1a[t]; b1b_s[t] = b1b[t]; c2a_s[t] = g_c2a[t]; }
    __syncthreads();

    int n = blockIdx.x * 256 + t;
    if (n >= NN) return;

    float tin[DIM];
    const float4* ay = (const float4*)(g_aggY + (size_t)n * DIM);
    const float4* yy = (const float4*)(g_y    + (size_t)n * DIM);
#pragma unroll
    for (int i = 0; i < 8; i++) {
        float4 a = ay[i], b = yy[i];
        tin[i*4+0] = fmaxf(a.x + b.x + b1a_s[i*4+0], 0.f);
        tin[i*4+1] = fmaxf(a.y + b.y + b1a_s[i*4+1], 0.f);
        tin[i*4+2] = fmaxf(a.z + b.z + b1a_s[i*4+2], 0.f);
        tin[i*4+3] = fmaxf(a.w + b.w + b1a_s[i*4+3], 0.f);
    }

    float h[DIM];
#pragma unroll
    for (int j = 0; j < DIM; j++) h[j] = b1b_s[j];
#pragma unroll
    for (int k = 0; k < DIM; k++) {
        float tk = tin[k];
#pragma unroll
        for (int j4 = 0; j4 < 8; j4++) {
            float4 w = w1b_s[k * 8 + j4];
            h[j4*4+0] += tk * w.x; h[j4*4+1] += tk * w.y;
            h[j4*4+2] += tk * w.z; h[j4*4+3] += tk * w.w;
        }
    }

    float z[DIM];
#pragma unroll
    for (int j = 0; j < DIM; j++) z[j] = c2a_s[j];
#pragma unroll
    for (int k = 0; k < DIM; k++) {
        float rk = fmaxf(h[k], 0.f);          // outer relu of layer 1
#pragma unroll
        for (int j4 = 0; j4 < 8; j4++) {
            float4 w = w2a_s[k * 8 + j4];
            z[j4*4+0] += rk * w.x; z[j4*4+1] += rk * w.y;
            z[j4*4+2] += rk * w.z; z[j4*4+3] += rk * w.w;
        }
    }

    float4* zr = (float4*)(g_z + (size_t)n * DIM);
#pragma unroll
    for (int j4 = 0; j4 < 8; j4++)
        zr[j4] = make_float4(z[4*j4], z[4*j4+1], z[4*j4+2], z[4*j4+3]);
}

// ---------------- K5: epilogue + log_softmax ----------------
__global__ void __launch_bounds__(256) k_final(const float* __restrict__ b2a,
                                               const float* __restrict__ fc1_w,
                                               const float* __restrict__ fc1_b,
                                               const float* __restrict__ fc2_w,
                                               const float* __restrict__ fc2_b,
                                               float* __restrict__ out) {
    __shared__ float4 w2b_s[DIM * 8];
    __shared__ float4 fc1_s[DIM * 8];
    __shared__ float4 fc2_s[DIM * NC / 4];
    __shared__ float b2a_s[DIM], bb2_s[DIM], fc1b_s[DIM], fc2b_s[NC];
    int t = threadIdx.x;
    for (int i = t; i < DIM * 8; i += 256) {
        w2b_s[i] = ((const float4*)g_W2b)[i];
        fc1_s[i] = ((const float4*)fc1_w)[i];
    }
    for (int i = t; i < DIM * NC / 4; i += 256)
        fc2_s[i] = ((const float4*)fc2_w)[i];
    if (t < DIM) { b2a_s[t] = b2a[t]; bb2_s[t] = g_bb2[t]; fc1b_s[t] = fc1_b[t]; }
    if (t < NC)  fc2b_s[t] = fc2_b[t];
    __syncthreads();

    int n = blockIdx.x * 256 + t;
    if (n >= NN) return;

    // q = relu(aggZ + z + b2a)
    float q[DIM];
    const float4* az = (const float4*)(g_aggZ + (size_t)n * DIM);
    const float4* zz = (const float4*)(g_z    + (size_t)n * DIM);
#pragma unroll
    for (int i = 0; i < 8; i++) {
        float4 a = az[i], b = zz[i];
        q[i*4+0] = fmaxf(a.x + b.x + b2a_s[i*4+0], 0.f);
        q[i*4+1] = fmaxf(a.y + b.y + b2a_s[i*4+1], 0.f);
        q[i*4+2] = fmaxf(a.z + b.z + b2a_s[i*4+2], 0.f);
        q[i*4+3] = fmaxf(a.w + b.w + b2a_s[i*4+3], 0.f);
    }

    // u = q @ W2b' + b2b'  (bn2 folded)
    float u[DIM];
#pragma unroll
    for (int j = 0; j < DIM; j++) u[j] = bb2_s[j];
#pragma unroll
    for (int k = 0; k < DIM; k++) {
        float qk = q[k];
#pragma unroll
        for (int j4 = 0; j4 < 8; j4++) {
            float4 w = w2b_s[k * 8 + j4];
            u[j4*4+0] += qk * w.x; u[j4*4+1] += qk * w.y;
            u[j4*4+2] += qk * w.z; u[j4*4+3] += qk * w.w;
        }
    }

    // r = relu(u @ fc1_w + fc1_b)
    float r[DIM];
#pragma unroll
    for (int j = 0; j < DIM; j++) r[j] = fc1b_s[j];
#pragma unroll
    for (int k = 0; k < DIM; k++) {
        float uk = u[k];
#pragma unroll
        for (int j4 = 0; j4 < 8; j4++) {
            float4 w = fc1_s[k * 8 + j4];
            r[j4*4+0] += uk * w.x; r[j4*4+1] += uk * w.y;
            r[j4*4+2] += uk * w.z; r[j4*4+3] += uk * w.w;
        }
    }
#pragma unroll
    for (int j = 0; j < DIM; j++) r[j] = fmaxf(r[j], 0.f);

    // logits = r @ fc2_w + fc2_b   (32 x 40)
    float l[NC];
#pragma unroll
    for (int c = 0; c < NC; c++) l[c] = fc2b_s[c];
#pragma unroll
    for (int k = 0; k < DIM; k++) {
        float rk = r[k];
#pragma unroll
        for (int c4 = 0; c4 < NC / 4; c4++) {
            float4 w = fc2_s[k * (NC / 4) + c4];
            l[c4*4+0] += rk * w.x; l[c4*4+1] += rk * w.y;
            l[c4*4+2] += rk * w.z; l[c4*4+3] += rk * w.w;
        }
    }

    // log_softmax
    float m = l[0];
#pragma unroll
    for (int c = 1; c < NC; c++) m = fmaxf(m, l[c]);
    float ssum = 0.f;
#pragma unroll
    for (int c = 0; c < NC; c++) ssum += expf(l[c] - m);
    float lse = m + logf(ssum);

    float4* orow = (float4*)(out + (size_t)n * NC);
#pragma unroll
    for (int c4 = 0; c4 < NC / 4; c4++)
        orow[c4] = make_float4(l[c4*4+0]-lse, l[c4*4+1]-lse, l[c4*4+2]-lse, l[c4*4+3]-lse);
}

// ---------------- launch ----------------
extern "C" void kernel_launch(void* const* d_in, const int* in_sizes, int n_in,
                              void* d_out, int out_size) {
    const float* x     = (const float*)d_in[0];
    const int*   ei32  = (const int*)d_in[1];       // int32 OR int64 (detected on device)
    const float* w1a   = (const float*)d_in[2];
    const float* b1a   = (const float*)d_in[3];
    const float* w1b   = (const float*)d_in[4];
    const float* b1b   = (const float*)d_in[5];
    const float* w2a   = (const float*)d_in[6];
    const float* b2a   = (const float*)d_in[7];
    const float* w2b   = (const float*)d_in[8];
    const float* b2b   = (const float*)d_in[9];
    const float* bn1_g = (const float*)d_in[10];
    const float* bn1_b = (const float*)d_in[11];
    const float* bn1_m = (const float*)d_in[12];
    const float* bn1_v = (const float*)d_in[13];
    const float* bn2_g = (const float*)d_in[14];
    const float* bn2_b = (const float*)d_in[15];
    const float* bn2_m = (const float*)d_in[16];
    const float* bn2_v = (const float*)d_in[17];
    const float* fc1_w = (const float*)d_in[18];
    const float* fc1_b = (const float*)d_in[19];
    const float* fc2_w = (const float*)d_in[20];
    const float* fc2_b = (const float*)d_in[21];
    float* out = (float*)d_out;

    const int NB_NODE = (NN + 255) / 256;
    const int NB_EDGE = (NE + 255) / 256;
    const int NB_ZERO = (NN * DIM / 4 + 255) / 256;

    k_detect<<<1, 32>>>(ei32);
    k_decode<<<NB_EDGE, 256>>>(ei32);
    k_setup<<<1, 1024>>>(w2a, bn1_g, bn1_b, bn1_m, bn1_v,
                         w2b, b2b, bn2_g, bn2_b, bn2_m, bn2_v);
    k_zero<<<NB_ZERO, 256>>>();
    k_gemm1<<<NB_NODE, 256>>>(x, w1a);
    k_agg<0><<<NB_EDGE, 256>>>();
    k_mlp1<<<NB_NODE, 256>>>(b1a, w1b, b1b);
    k_agg<1><<<NB_EDGE, 256>>>();
    k_final<<<NB_NODE, 256>>>(b2a, fc1_w, fc1_b, fc2_w, fc2_b, out);
}